// round 15
// baseline (speedup 1.0000x reference)
#include <cuda_runtime.h>
#include <cuda_fp16.h>
#include <math.h>
#include <stdint.h>

// Qwen3 MoE gate, two-kernel: (A) 1-pass fp16 mma.sync GEMM -> approx logits
// in a __device__ buffer (DRAM-bound, 8-warp CTAs, 2/SM);  (B) warp-per-token
// top-10 + exact fp32 refinement of near-ties (gap < THETA) + top-8 softmax
// renorm (high-occupancy, latency-tolerant).
// Output: [idx f32 (T*8) | weights (T*8)].

#define HDIM 2048
#define NEXP 128
#define TDIM 16384
#define BM   64
#define BK   64
#define NCH  (HDIM / BK)          // 32
#define NTHR 256
#define TOPK 8
#define NCAND 10
#define THETA 4e-3f

#define XTILE_B  (BM * 128)       // 8KB
#define WTILE_B  (NEXP * 128)     // 16KB
#define OFF_XH   0
#define OFF_WH   XTILE_B
#define STAGE_B  (XTILE_B + WTILE_B)   // 24KB
#define SMEM_TOT (2 * STAGE_B)         // 48KB

__device__ __half g_wh[NEXP * HDIM];
__device__ float  g_lg[TDIM * NEXP];   // approx logits (8MB)

__device__ __forceinline__ uint32_t smem_u32(const void* p) {
    uint32_t a;
    asm("{ .reg .u64 t; cvta.to.shared.u64 t, %1; cvt.u32.u64 %0, t; }"
        : "=r"(a) : "l"(p));
    return a;
}

#define SWZ(o) ((o) ^ ((((uint32_t)(o)) >> 3) & 0x70))

#define CP16(dst, src) \
    asm volatile("cp.async.cg.shared.global [%0], [%1], 16;" \
                 :: "r"(dst), "l"(src))
#define CP_COMMIT() asm volatile("cp.async.commit_group;" ::: "memory")
#define CP_WAIT0()  asm volatile("cp.async.wait_group 0;" ::: "memory")

#define LDM4(R, a) \
    asm volatile("ldmatrix.sync.aligned.m8n8.x4.shared.b16 {%0,%1,%2,%3}, [%4];" \
                 : "=r"((R)[0]), "=r"((R)[1]), "=r"((R)[2]), "=r"((R)[3])      \
                 : "r"(a))

#define MMA(d, a, b0, b1) \
    asm volatile("mma.sync.aligned.m16n8k16.row.col.f32.f16.f16.f32 "          \
                 "{%0,%1,%2,%3}, {%4,%5,%6,%7}, {%8,%9}, {%0,%1,%2,%3};"       \
                 : "+f"((d)[0]), "+f"((d)[1]), "+f"((d)[2]), "+f"((d)[3])      \
                 : "r"((a)[0]), "r"((a)[1]), "r"((a)[2]), "r"((a)[3]),         \
                   "r"(b0), "r"(b1))

__device__ __forceinline__ uint32_t pack_h2(float a, float b) {
    __half2 h = __floats2half2_rn(a, b);
    return *(uint32_t*)&h;
}

// -------- prep: W -> fp16 --------
__global__ void prep_w_kernel(const float* __restrict__ w) {
    int i = blockIdx.x * blockDim.x + threadIdx.x;
    float4 v = ((const float4*)w)[i];
    uint2 hi;
    hi.x = pack_h2(v.x, v.y);
    hi.y = pack_h2(v.z, v.w);
    ((uint2*)g_wh)[i] = hi;
}

// ================= Kernel A: 1-pass fp16 GEMM =================
__global__ __launch_bounds__(NTHR, 2)
void gemm_kernel(const float* __restrict__ x)
{
    extern __shared__ char smem[];
    const uint32_t sb = smem_u32(smem);
    const int tid  = threadIdx.x;
    const int lane = tid & 31;
    const int wid  = tid >> 5;
    const int bm   = blockIdx.x * BM;

    float acc[2][4][4];
#pragma unroll
    for (int i = 0; i < 2; i++)
#pragma unroll
        for (int j = 0; j < 4; j++)
#pragma unroll
            for (int r = 0; r < 4; r++) acc[i][j][r] = 0.f;

    // x loader: 64 rows x 16 float4 = 1024; 4 per thread
    int xrow[4];
#pragma unroll
    for (int j = 0; j < 4; j++) xrow[j] = (tid + j * NTHR) >> 4;
    const int xq = tid & 15;
    const float* xg = x + (size_t)bm * HDIM;

    // W loader: 128 rows x 8 lines = 1024; 4 per thread
    int wrow[4];
#pragma unroll
    for (int j = 0; j < 4; j++) wrow[j] = (tid + j * NTHR) >> 3;
    const int ws = tid & 7;

    // 8 warps: 2(M) x 4(N), warp tile 32x32
    const int wm = (wid & 1) * 32;
    const int wn = (wid >> 1) * 32;
    const int aRow = (lane & 7) + ((lane >> 3) & 1) * 8;
    const int aKB  = ((lane >> 4) & 1) * 16;
    const int bRow = (lane & 7) + ((lane >> 4) & 1) * 8;
    const int bKB  = ((lane >> 3) & 1) * 16;

#define ISSUE_W(c, stg) do {                                                   \
    _Pragma("unroll")                                                          \
    for (int j = 0; j < 4; j++) {                                              \
        uint32_t o  = SWZ((uint32_t)(wrow[j] * 128 + ws * 16));                \
        const __half* sh = g_wh + (size_t)wrow[j] * HDIM + (c) * BK + ws * 8;  \
        CP16(sb + (stg) + OFF_WH + o, sh);                                     \
    }                                                                          \
    CP_COMMIT();                                                               \
} while (0)

#define LOAD_X(c, xr) do {                                                     \
    _Pragma("unroll")                                                          \
    for (int j = 0; j < 4; j++)                                                \
        xr[j] = *(const float4*)(xg + (size_t)xrow[j] * HDIM + (c) * BK + xq * 4); \
} while (0)

#define STORE_X(xr, stg) do {                                                  \
    _Pragma("unroll")                                                          \
    for (int j = 0; j < 4; j++) {                                              \
        float4 v = xr[j];                                                      \
        uint2 hi;                                                              \
        hi.x = pack_h2(v.x, v.y);  hi.y = pack_h2(v.z, v.w);                   \
        uint32_t o = SWZ((uint32_t)(xrow[j] * 128 + xq * 8));                  \
        *(uint2*)(smem + (stg) + OFF_XH + o) = hi;                             \
    }                                                                          \
} while (0)

    {
        float4 xr[4];
        ISSUE_W(0, 0);
        LOAD_X(0, xr);
        STORE_X(xr, 0);
        CP_WAIT0();
        __syncthreads();
    }

    for (int c = 0; c < NCH; c++) {
        const uint32_t stg  = (uint32_t)((c & 1) ? STAGE_B : 0);
        const uint32_t nstg = stg ^ STAGE_B;
        float4 xr[4];
        if (c + 1 < NCH) {
            ISSUE_W(c + 1, nstg);
            LOAD_X(c + 1, xr);
        }

#pragma unroll
        for (int ks = 0; ks < 4; ks++) {
            uint32_t Ah[2][4], Bh[2][4];
#pragma unroll
            for (int mt = 0; mt < 2; mt++) {
                uint32_t o = SWZ((uint32_t)((wm + mt * 16 + aRow) * 128 + ks * 32 + aKB));
                LDM4(Ah[mt], sb + stg + OFF_XH + o);
            }
#pragma unroll
            for (int p = 0; p < 2; p++) {
                uint32_t o = SWZ((uint32_t)((wn + p * 16 + bRow) * 128 + ks * 32 + bKB));
                LDM4(Bh[p], sb + stg + OFF_WH + o);
            }
#pragma unroll
            for (int mt = 0; mt < 2; mt++)
#pragma unroll
                for (int nt = 0; nt < 4; nt++) {
                    const int p = nt >> 1, r0 = (nt & 1) * 2;
                    MMA(acc[mt][nt], Ah[mt], Bh[p][r0], Bh[p][r0 + 1]);
                }
        }

        if (c + 1 < NCH) STORE_X(xr, nstg);
        CP_WAIT0();
        __syncthreads();
    }

    // write approx logits
    {
        const int r0 = lane >> 2;
        const int c0 = (lane & 3) * 2;
#pragma unroll
        for (int mt = 0; mt < 2; mt++)
#pragma unroll
            for (int nt = 0; nt < 4; nt++) {
                int row = bm + wm + mt * 16 + r0;
                int col = wn + nt * 8 + c0;
                *(float2*)&g_lg[(size_t)row * NEXP + col] =
                    make_float2(acc[mt][nt][0], acc[mt][nt][1]);
                *(float2*)&g_lg[(size_t)(row + 8) * NEXP + col] =
                    make_float2(acc[mt][nt][2], acc[mt][nt][3]);
            }
    }
}

// ================= Kernel B: warp-per-token top-k =================
__global__ __launch_bounds__(256)
void topk_kernel(const float* __restrict__ x, const float* __restrict__ w,
                 float* __restrict__ out, int T)
{
    const int lane  = threadIdx.x & 31;
    const int token = blockIdx.x * 8 + (threadIdx.x >> 5);

    float4 lv = ((const float4*)(g_lg + (size_t)token * NEXP))[lane];
    float v[4] = { lv.x, lv.y, lv.z, lv.w };

    float cv[NCAND];
    int   cid[NCAND];
#pragma unroll
    for (int j = 0; j < NCAND; j++) {
        float bv = v[0];
        int   bi = 0;
#pragma unroll
        for (int r = 1; r < 4; r++)
            if (v[r] > bv) { bv = v[r]; bi = r; }
        int gi = lane * 4 + bi;
#pragma unroll
        for (int o = 16; o; o >>= 1) {
            float ov = __shfl_xor_sync(0xffffffffu, bv, o);
            int   oi = __shfl_xor_sync(0xffffffffu, gi, o);
            if (ov > bv || (ov == bv && oi < gi)) { bv = ov; gi = oi; }
        }
        cv[j] = bv; cid[j] = gi;
        if ((gi >> 2) == lane) v[gi & 3] = -INFINITY;
    }

    // near-tie refinement: exact fp32 dot for marked slots
    unsigned need = 0;
#pragma unroll
    for (int j = 0; j < NCAND - 1; j++)
        if (cv[j] - cv[j + 1] < THETA) need |= (3u << j);
#pragma unroll
    for (int j = 0; j < NCAND; j++)
        if (need & (1u << j)) {
            const float4* xr = (const float4*)(x + (size_t)token * HDIM) + lane;
            const float4* wr = (const float4*)(w + (size_t)cid[j] * HDIM) + lane;
            float s = 0.f;
#pragma unroll
            for (int it = 0; it < 16; it++) {
                float4 a = xr[it * 32];
                float4 b = wr[it * 32];
                s += a.x * b.x + a.y * b.y + a.z * b.z + a.w * b.w;
            }
#pragma unroll
            for (int o = 16; o; o >>= 1)
                s += __shfl_xor_sync(0xffffffffu, s, o);
            cv[j] = s;
        }

    // final top-8 (value desc, index asc on ties), softmax renorm
    unsigned used = 0;
    int   ids[TOPK];
    float vals[TOPK];
#pragma unroll
    for (int kk = 0; kk < TOPK; kk++) {
        float best = -INFINITY;
        int   bj = 0, bid = NEXP;
#pragma unroll
        for (int j = 0; j < NCAND; j++) {
            if (used & (1u << j)) continue;
            if (cv[j] > best || (cv[j] == best && cid[j] < bid)) {
                best = cv[j]; bj = j; bid = cid[j];
            }
        }
        used |= (1u << bj);
        ids[kk]  = bid;
        vals[kk] = best;
    }
    if (lane == 0) {
        const float m0 = vals[0];
        float wts[TOPK], sum = 0.f;
#pragma unroll
        for (int kk = 0; kk < TOPK; kk++) {
            float e = expf(vals[kk] - m0);
            wts[kk] = e;
            sum += e;
        }
        float* out_idx = out + (size_t)token * TOPK;
        float* out_wt  = out + (size_t)T * TOPK + (size_t)token * TOPK;
#pragma unroll
        for (int kk = 0; kk < TOPK; kk++) {
            out_idx[kk] = (float)ids[kk];
            out_wt [kk] = wts[kk] / sum;
        }
    }
}

extern "C" void kernel_launch(void* const* d_in, const int* in_sizes, int n_in,
                              void* d_out, int out_size)
{
    const float* x = (const float*)d_in[0];   // [4,4096,2048] fp32
    const float* w = (const float*)d_in[1];   // [128,2048]    fp32
    float* out = (float*)d_out;

    const int T = in_sizes[0] / HDIM;         // 16384

    prep_w_kernel<<<(NEXP * HDIM / 4) / 256, 256>>>(w);

    cudaFuncSetAttribute(gemm_kernel,
                         cudaFuncAttributeMaxDynamicSharedMemorySize, SMEM_TOT);
    gemm_kernel<<<T / BM, NTHR, SMEM_TOT>>>(x);

    topk_kernel<<<T / 8, 256>>>(x, w, out, T);
}